// round 1
// baseline (speedup 1.0000x reference)
#include <cuda_runtime.h>
#include <math.h>

#define BATCH 2
#define SEQ   4096
#define DIM   512

// Scratch in device globals (no allocations allowed).
__device__ float g_Q[BATCH * SEQ * DIM];
__device__ float g_K[BATCH * SEQ * DIM];
__device__ float g_V[BATCH * SEQ * DIM];
__device__ float g_P[(long long)BATCH * SEQ * SEQ];

// ---------------------------------------------------------------------------
// Generic tiled fp32 GEMM.
//   C[M,N] = alpha * A[M,K] @ op(B)        (row-major everywhere)
//   TRANSB=false : B is [K,N]   (NN)
//   TRANSB=true  : B is [N,K]   (NT, i.e. A @ B^T)
// BM=128, BN=64, BK=16, 256 threads, 8x4 per-thread microtile.
// All problem dims are multiples of the tile sizes -> no bounds checks.
// ---------------------------------------------------------------------------
template <bool TRANSB>
__global__ __launch_bounds__(256)
void gemm_kernel(const float* __restrict__ A,
                 const float* __restrict__ Bm,
                 float* __restrict__ C,
                 int M, int N, int K,
                 long long sA, long long sB, long long sC,
                 float alpha)
{
    constexpr int BM = 128, BN = 64, BK = 16, TM = 8, TN = 4;
    __shared__ float As[BK][BM + 4];
    __shared__ float Bs[BK][BN + 4];

    const int bz = blockIdx.z;
    A  += bz * sA;
    Bm += bz * sB;
    C  += bz * sC;

    const int bm  = blockIdx.y * BM;
    const int bn  = blockIdx.x * BN;
    const int tid = threadIdx.x;          // 0..255
    const int tx  = tid & 15;             // N direction (16 * TN = 64)
    const int ty  = tid >> 4;             // M direction (16 * TM = 128)

    float acc[TM][TN];
#pragma unroll
    for (int i = 0; i < TM; i++)
#pragma unroll
        for (int j = 0; j < TN; j++) acc[i][j] = 0.f;

    for (int k0 = 0; k0 < K; k0 += BK) {
        // ---- load A tile [BM][BK] -> As[k][m] (transposed) ----
#pragma unroll
        for (int r = 0; r < 2; r++) {
            int c    = tid + r * 256;     // float4 chunk id, 0..511
            int row  = c >> 2;            // 0..127
            int col4 = (c & 3) * 4;       // 0,4,8,12
            float4 v = *reinterpret_cast<const float4*>(
                &A[(long long)(bm + row) * K + k0 + col4]);
            As[col4 + 0][row] = v.x;
            As[col4 + 1][row] = v.y;
            As[col4 + 2][row] = v.z;
            As[col4 + 3][row] = v.w;
        }
        // ---- load B tile -> Bs[k][n] ----
        if (TRANSB) {
            // B is [N,K]; tile [BN][BK], transpose on store
            int row  = tid >> 2;          // 0..63
            int col4 = (tid & 3) * 4;     // 0,4,8,12
            float4 v = *reinterpret_cast<const float4*>(
                &Bm[(long long)(bn + row) * K + k0 + col4]);
            Bs[col4 + 0][row] = v.x;
            Bs[col4 + 1][row] = v.y;
            Bs[col4 + 2][row] = v.z;
            Bs[col4 + 3][row] = v.w;
        } else {
            // B is [K,N]; tile [BK][BN], direct store
            int row  = tid >> 4;          // 0..15
            int col4 = (tid & 15) * 4;    // 0..60
            float4 v = *reinterpret_cast<const float4*>(
                &Bm[(long long)(k0 + row) * N + bn + col4]);
            Bs[row][col4 + 0] = v.x;
            Bs[row][col4 + 1] = v.y;
            Bs[row][col4 + 2] = v.z;
            Bs[row][col4 + 3] = v.w;
        }
        __syncthreads();

#pragma unroll
        for (int kk = 0; kk < BK; kk++) {
            float a[TM], b[TN];
#pragma unroll
            for (int i = 0; i < TM; i++) a[i] = As[kk][ty * TM + i];
#pragma unroll
            for (int j = 0; j < TN; j++) b[j] = Bs[kk][tx * TN + j];
#pragma unroll
            for (int i = 0; i < TM; i++)
#pragma unroll
                for (int j = 0; j < TN; j++)
                    acc[i][j] += a[i] * b[j];
        }
        __syncthreads();
    }

#pragma unroll
    for (int i = 0; i < TM; i++) {
        long long crow = bm + ty * TM + i;
#pragma unroll
        for (int j = 0; j < TN; j++)
            C[crow * N + bn + tx * TN + j] = acc[i][j] * alpha;
    }
}

// ---------------------------------------------------------------------------
// Row softmax over rows of length SEQ=4096. One block (256 thr) per row,
// 16 elements per thread kept in registers.
// ---------------------------------------------------------------------------
__global__ __launch_bounds__(256)
void softmax_kernel(float* __restrict__ P)
{
    const long long row = blockIdx.x;
    float* p = P + row * (long long)SEQ;
    const int tid = threadIdx.x;

    __shared__ float redmax[8];
    __shared__ float redsum[8];

    float v[16];
    float m = -1e30f;
#pragma unroll
    for (int i = 0; i < 16; i++) {
        v[i] = p[tid + i * 256];
        m = fmaxf(m, v[i]);
    }
    // block max
#pragma unroll
    for (int o = 16; o > 0; o >>= 1) m = fmaxf(m, __shfl_xor_sync(0xffffffffu, m, o));
    if ((tid & 31) == 0) redmax[tid >> 5] = m;
    __syncthreads();
    {
        float t = (tid < 8) ? redmax[tid] : -1e30f;
#pragma unroll
        for (int o = 4; o > 0; o >>= 1) t = fmaxf(t, __shfl_xor_sync(0xffffffffu, t, o));
        if (tid == 0) redmax[0] = t;
    }
    __syncthreads();
    m = redmax[0];

    float s = 0.f;
#pragma unroll
    for (int i = 0; i < 16; i++) {
        v[i] = __expf(v[i] - m);
        s += v[i];
    }
#pragma unroll
    for (int o = 16; o > 0; o >>= 1) s += __shfl_xor_sync(0xffffffffu, s, o);
    if ((tid & 31) == 0) redsum[tid >> 5] = s;
    __syncthreads();
    {
        float t = (tid < 8) ? redsum[tid] : 0.f;
#pragma unroll
        for (int o = 4; o > 0; o >>= 1) t += __shfl_xor_sync(0xffffffffu, t, o);
        if (tid == 0) redsum[0] = t;
    }
    __syncthreads();
    const float inv = 1.f / redsum[0];

#pragma unroll
    for (int i = 0; i < 16; i++)
        p[tid + i * 256] = v[i] * inv;
}

// ---------------------------------------------------------------------------
extern "C" void kernel_launch(void* const* d_in, const int* in_sizes, int n_in,
                              void* d_out, int out_size)
{
    const float* x  = (const float*)d_in[0];  // [B,S,D]
    const float* Wq = (const float*)d_in[1];  // [D,D]
    const float* Wk = (const float*)d_in[2];
    const float* Wv = (const float*)d_in[3];
    float* out = (float*)d_out;               // [B,S,D]

    float *q, *k, *v, *p;
    cudaGetSymbolAddress((void**)&q, g_Q);
    cudaGetSymbolAddress((void**)&k, g_K);
    cudaGetSymbolAddress((void**)&v, g_V);
    cudaGetSymbolAddress((void**)&p, g_P);

    const int M  = BATCH * SEQ;               // 8192
    const long long sQKV = (long long)SEQ * DIM;      // 2,097,152
    const long long sP   = (long long)SEQ * SEQ;      // 16,777,216

    // 1-3. Projections: [8192,512] @ [512,512] (NN)
    dim3 gProj(DIM / 64, M / 128, 1);
    gemm_kernel<false><<<gProj, 256>>>(x, Wq, q, M, DIM, DIM, 0, 0, 0, 1.f);
    gemm_kernel<false><<<gProj, 256>>>(x, Wk, k, M, DIM, DIM, 0, 0, 0, 1.f);
    gemm_kernel<false><<<gProj, 256>>>(x, Wv, v, M, DIM, DIM, 0, 0, 0, 1.f);

    // 4. Scores: per batch, [4096,512] @ [4096,512]^T * 1/sqrt(512) (NT)
    const float scale = 0.044194173824159216f;  // 1/sqrt(512)
    dim3 gScores(SEQ / 64, SEQ / 128, BATCH);
    gemm_kernel<true><<<gScores, 256>>>(q, k, p, SEQ, SEQ, DIM, sQKV, sQKV, sP, scale);

    // 5. Softmax over last dim (8192 rows of 4096)
    softmax_kernel<<<BATCH * SEQ, 256>>>(p);

    // 6. Context: per batch, [4096,4096] @ [4096,512] (NN) -> d_out
    dim3 gPV(DIM / 64, SEQ / 128, BATCH);
    gemm_kernel<false><<<gPV, 256>>>(p, v, out, SEQ, DIM, SEQ, sP, sQKV, sQKV, 1.f);

    (void)in_sizes; (void)n_in; (void)out_size;
}

// round 3
// speedup vs baseline: 2.3327x; 2.3327x over previous
#include <cuda_runtime.h>
#include <cuda_bf16.h>
#include <cstdint>

#define BATCH 2
#define SEQ   4096
#define DIM   512
#define MTOT  (BATCH*SEQ)   // 8192

// ---------------------------------------------------------------------------
// Scratch (device globals; no allocations allowed)
// ---------------------------------------------------------------------------
__device__ __align__(128) __nv_bfloat16 g_xh[MTOT*DIM], g_xl[MTOT*DIM];
__device__ __align__(128) __nv_bfloat16 g_Wqh[DIM*DIM], g_Wql[DIM*DIM];
__device__ __align__(128) __nv_bfloat16 g_Wkh[DIM*DIM], g_Wkl[DIM*DIM];
__device__ __align__(128) __nv_bfloat16 g_Wvh[DIM*DIM], g_Wvl[DIM*DIM];
__device__ __align__(128) __nv_bfloat16 g_Qh[MTOT*DIM],  g_Ql[MTOT*DIM];
__device__ __align__(128) __nv_bfloat16 g_Kh[MTOT*DIM],  g_Kl[MTOT*DIM];
__device__ __align__(128) __nv_bfloat16 g_VTh[MTOT*DIM], g_VTl[MTOT*DIM];  // [B][DIM][SEQ]
__device__ __align__(128) float         g_P [(long long)BATCH*SEQ*SEQ];
__device__ __align__(128) __nv_bfloat16 g_Ph[(long long)BATCH*SEQ*SEQ];
__device__ __align__(128) __nv_bfloat16 g_Pl[(long long)BATCH*SEQ*SEQ];

// ---------------------------------------------------------------------------
// PTX helpers (sm_80-era ISA only: mma.sync / ldmatrix / cp.async)
// ---------------------------------------------------------------------------
__device__ __forceinline__ uint32_t smem_u32(const void* p) {
    uint32_t a;
    asm("{ .reg .u64 t; cvta.to.shared.u64 t, %1; cvt.u32.u64 %0, t; }"
        : "=r"(a) : "l"(p));
    return a;
}

__device__ __forceinline__ void cp_async16(uint32_t saddr, const void* gptr) {
    asm volatile("cp.async.cg.shared.global [%0], [%1], 16;"
                 :: "r"(saddr), "l"(gptr) : "memory");
}
#define CP_COMMIT()  asm volatile("cp.async.commit_group;" ::: "memory")
#define CP_WAIT(n)   asm volatile("cp.async.wait_group %0;" :: "n"(n) : "memory")

__device__ __forceinline__ void ldsm_x4(uint32_t* r, uint32_t addr) {
    asm volatile("ldmatrix.sync.aligned.m8n8.x4.shared.b16 {%0,%1,%2,%3}, [%4];"
                 : "=r"(r[0]), "=r"(r[1]), "=r"(r[2]), "=r"(r[3]) : "r"(addr));
}
__device__ __forceinline__ void ldsm_x2(uint32_t* r, uint32_t addr) {
    asm volatile("ldmatrix.sync.aligned.m8n8.x2.shared.b16 {%0,%1}, [%2];"
                 : "=r"(r[0]), "=r"(r[1]) : "r"(addr));
}

__device__ __forceinline__ void mma16816(float* c, const uint32_t* a, const uint32_t* b) {
    asm volatile(
        "mma.sync.aligned.m16n8k16.row.col.f32.bf16.bf16.f32 "
        "{%0,%1,%2,%3}, {%4,%5,%6,%7}, {%8,%9}, {%0,%1,%2,%3};"
        : "+f"(c[0]), "+f"(c[1]), "+f"(c[2]), "+f"(c[3])
        : "r"(a[0]), "r"(a[1]), "r"(a[2]), "r"(a[3]), "r"(b[0]), "r"(b[1]));
}

// ---------------------------------------------------------------------------
// bf16x2-split GEMM on mma.sync:  C[M,N] = alpha * (A[M,K] @ B[N,K]^T)
// A = (Ah,Al), B = (Bh,Bl); product = hh + hl + lh (ll dropped).
// BM=BN=128, BK=32, 256 threads (8 warps: 2 M x 4 N), warp tile 64x32.
// Double-buffered cp.async, smem rows pitch 80B (conflict-free ldmatrix).
// EPI: 0 = fp32 C, 1 = split bf16 (Ch,Cl), 2 = split + V^T layout.
// ---------------------------------------------------------------------------
constexpr int PITCH   = 80;              // 64B data + 16B pad
constexpr int TILE_B  = 128 * PITCH;     // 10240 B per tile
constexpr int STAGE_B = 4 * TILE_B;      // Ah, Al, Bh, Bl
constexpr int SMEM_BYTES = 2 * STAGE_B;  // 81920 B

template <int EPI>
__global__ __launch_bounds__(256)
void tc_gemm(const __nv_bfloat16* __restrict__ Ah, const __nv_bfloat16* __restrict__ Al,
             const __nv_bfloat16* __restrict__ Bh, const __nv_bfloat16* __restrict__ Bl,
             float* __restrict__ C,
             __nv_bfloat16* __restrict__ Ch, __nv_bfloat16* __restrict__ Cl,
             int M, int N, int K,
             long long sA, long long sB, long long sC, float alpha)
{
    extern __shared__ __align__(128) char smem[];
    const uint32_t sb = smem_u32(smem);
    const int tid  = threadIdx.x;
    const int wid  = tid >> 5;
    const int lane = tid & 31;
    const int z = blockIdx.z;
    Ah += z * sA;  Al += z * sA;
    Bh += z * sB;  Bl += z * sB;

    const long long bm = (long long)blockIdx.y * 128;
    const long long bn = (long long)blockIdx.x * 128;

    const __nv_bfloat16* srcs[4] = {
        Ah + bm * K, Al + bm * K, Bh + bn * K, Bl + bn * K };

    // ---- async tile loader: 4 tiles x 512 16B-chunks, 8 chunks/thread ----
    auto issue_load = [&](int it, int buf) {
        const uint32_t stage = sb + buf * STAGE_B;
        const int k0 = it * 32;
#pragma unroll
        for (int t = 0; t < 4; ++t) {
            const __nv_bfloat16* src = srcs[t] + k0;
#pragma unroll
            for (int c = 0; c < 2; ++c) {
                const int chunk = tid + c * 256;        // 0..511
                const int row = chunk >> 2;
                const int c4  = chunk & 3;
                cp_async16(stage + t * TILE_B + row * PITCH + c4 * 16,
                           src + (long long)row * K + c4 * 8);
            }
        }
    };

    const int warpM = wid >> 2;        // 0..1  (64 rows each)
    const int warpN = wid & 3;         // 0..3  (32 cols each)

    // ldmatrix lane address components
    const int aRow = warpM * 64 + (lane & 15);
    const int aOff = (lane >> 4) * 16;
    const int bRow = warpN * 32 + (lane & 7);
    const int bOff = ((lane >> 3) & 1) * 16;

    float acc[4][4][4];
#pragma unroll
    for (int mi = 0; mi < 4; ++mi)
#pragma unroll
        for (int ni = 0; ni < 4; ++ni)
#pragma unroll
            for (int q = 0; q < 4; ++q) acc[mi][ni][q] = 0.f;

    const int niter = K / 32;
    issue_load(0, 0); CP_COMMIT();
    if (niter > 1) issue_load(1, 1);
    CP_COMMIT();

    for (int it = 0; it < niter; ++it) {
        const int buf = it & 1;
        CP_WAIT(1);
        __syncthreads();

        const uint32_t stage = sb + buf * STAGE_B;
        const uint32_t aBaseH = stage + 0 * TILE_B + aRow * PITCH + aOff;
        const uint32_t aBaseL = stage + 1 * TILE_B + aRow * PITCH + aOff;
        const uint32_t bBaseH = stage + 2 * TILE_B + bRow * PITCH + bOff;
        const uint32_t bBaseL = stage + 3 * TILE_B + bRow * PITCH + bOff;

#pragma unroll
        for (int ks = 0; ks < 2; ++ks) {
            uint32_t ah[4][4], al[4][4], bh[4][2], bl[4][2];
#pragma unroll
            for (int mi = 0; mi < 4; ++mi) {
                ldsm_x4(ah[mi], aBaseH + mi * (16 * PITCH) + ks * 32);
                ldsm_x4(al[mi], aBaseL + mi * (16 * PITCH) + ks * 32);
            }
#pragma unroll
            for (int ni = 0; ni < 4; ++ni) {
                ldsm_x2(bh[ni], bBaseH + ni * (8 * PITCH) + ks * 32);
                ldsm_x2(bl[ni], bBaseL + ni * (8 * PITCH) + ks * 32);
            }
#pragma unroll
            for (int mi = 0; mi < 4; ++mi)
#pragma unroll
                for (int ni = 0; ni < 4; ++ni) {
                    mma16816(acc[mi][ni], ah[mi], bh[ni]);
                    mma16816(acc[mi][ni], ah[mi], bl[ni]);
                    mma16816(acc[mi][ni], al[mi], bh[ni]);
                }
        }
        __syncthreads();
        if (it + 2 < niter) issue_load(it + 2, buf);
        CP_COMMIT();
    }

    // ---- epilogue ----
    const int r0 = warpM * 64 + (lane >> 2);
    const int c0 = warpN * 32 + (lane & 3) * 2;
#pragma unroll
    for (int mi = 0; mi < 4; ++mi) {
#pragma unroll
        for (int ni = 0; ni < 4; ++ni) {
#pragma unroll
            for (int h = 0; h < 2; ++h) {
                const long long row = bm + r0 + mi * 16 + h * 8;
                const int col = (int)bn + c0 + ni * 8;
                const float f0 = acc[mi][ni][2 * h]     * alpha;
                const float f1 = acc[mi][ni][2 * h + 1] * alpha;
                if (EPI == 0) {
                    float2 v; v.x = f0; v.y = f1;
                    *reinterpret_cast<float2*>(C + z * sC + row * N + col) = v;
                } else if (EPI == 1) {
                    __nv_bfloat16 h0 = __float2bfloat16(f0);
                    __nv_bfloat16 l0 = __float2bfloat16(f0 - __bfloat162float(h0));
                    __nv_bfloat16 h1 = __float2bfloat16(f1);
                    __nv_bfloat16 l1 = __float2bfloat16(f1 - __bfloat162float(h1));
                    __nv_bfloat162 vh; vh.x = h0; vh.y = h1;
                    __nv_bfloat162 vl; vl.x = l0; vl.y = l1;
                    *reinterpret_cast<__nv_bfloat162*>(Ch + row * N + col) = vh;
                    *reinterpret_cast<__nv_bfloat162*>(Cl + row * N + col) = vl;
                } else {
                    // V^T layout [B][DIM][SEQ]; row = token, col = d
                    const long long bimg = (row >> 12) * ((long long)DIM * SEQ);
                    const int s = (int)(row & (SEQ - 1));
                    __nv_bfloat16 h0 = __float2bfloat16(f0);
                    __nv_bfloat16 l0 = __float2bfloat16(f0 - __bfloat162float(h0));
                    __nv_bfloat16 h1 = __float2bfloat16(f1);
                    __nv_bfloat16 l1 = __float2bfloat16(f1 - __bfloat162float(h1));
                    Ch[bimg + (long long)col * SEQ + s]       = h0;
                    Cl[bimg + (long long)col * SEQ + s]       = l0;
                    Ch[bimg + (long long)(col + 1) * SEQ + s] = h1;
                    Cl[bimg + (long long)(col + 1) * SEQ + s] = l1;
                }
            }
        }
    }
}

// ---------------------------------------------------------------------------
// fp32 -> bf16 hi/lo split (elementwise, float4 vectorized)
// ---------------------------------------------------------------------------
__global__ __launch_bounds__(256)
void split_kernel(const float* __restrict__ in,
                  __nv_bfloat16* __restrict__ hi, __nv_bfloat16* __restrict__ lo, int n4)
{
    const int i = blockIdx.x * blockDim.x + threadIdx.x;
    if (i >= n4) return;
    float4 v = *reinterpret_cast<const float4*>(in + 4 * (long long)i);
    float f[4] = { v.x, v.y, v.z, v.w };
    __nv_bfloat16 h[4], l[4];
#pragma unroll
    for (int q = 0; q < 4; ++q) {
        h[q] = __float2bfloat16(f[q]);
        l[q] = __float2bfloat16(f[q] - __bfloat162float(h[q]));
    }
    __nv_bfloat162 h01, h23, l01, l23;
    h01.x = h[0]; h01.y = h[1]; h23.x = h[2]; h23.y = h[3];
    l01.x = l[0]; l01.y = l[1]; l23.x = l[2]; l23.y = l[3];
    *reinterpret_cast<__nv_bfloat162*>(hi + 4 * (long long)i)     = h01;
    *reinterpret_cast<__nv_bfloat162*>(hi + 4 * (long long)i + 2) = h23;
    *reinterpret_cast<__nv_bfloat162*>(lo + 4 * (long long)i)     = l01;
    *reinterpret_cast<__nv_bfloat162*>(lo + 4 * (long long)i + 2) = l23;
}

// ---------------------------------------------------------------------------
// W[i][o] -> W^T[o][i], split to bf16 hi/lo.  512x512.
// ---------------------------------------------------------------------------
__global__ __launch_bounds__(256)
void wtrans_split(const float* __restrict__ W,
                  __nv_bfloat16* __restrict__ Th, __nv_bfloat16* __restrict__ Tl)
{
    __shared__ float t[32][33];
    const int bx = blockIdx.x * 32;   // o
    const int by = blockIdx.y * 32;   // i
    const int tx = threadIdx.x, ty = threadIdx.y;   // 32 x 8
#pragma unroll
    for (int r = ty; r < 32; r += 8)
        t[r][tx] = W[(by + r) * DIM + bx + tx];
    __syncthreads();
#pragma unroll
    for (int r = ty; r < 32; r += 8) {
        const float f = t[tx][r];                    // = W[by+tx][bx+r]
        __nv_bfloat16 h = __float2bfloat16(f);
        __nv_bfloat16 l = __float2bfloat16(f - __bfloat162float(h));
        Th[(bx + r) * DIM + by + tx] = h;
        Tl[(bx + r) * DIM + by + tx] = l;
    }
}

// ---------------------------------------------------------------------------
// Row softmax over 4096-wide rows; writes bf16 hi/lo split directly.
// ---------------------------------------------------------------------------
__global__ __launch_bounds__(256)
void softmax_split(const float* __restrict__ P,
                   __nv_bfloat16* __restrict__ Ph, __nv_bfloat16* __restrict__ Pl)
{
    const long long row = blockIdx.x;
    const float* p = P + row * (long long)SEQ;
    const int tid = threadIdx.x;

    __shared__ float red[8];

    float v[16];
#pragma unroll
    for (int i = 0; i < 4; ++i)
        *reinterpret_cast<float4*>(v + 4 * i) =
            *reinterpret_cast<const float4*>(p + i * 1024 + tid * 4);

    float m = -1e30f;
#pragma unroll
    for (int i = 0; i < 16; ++i) m = fmaxf(m, v[i]);
#pragma unroll
    for (int o = 16; o > 0; o >>= 1) m = fmaxf(m, __shfl_xor_sync(0xffffffffu, m, o));
    if ((tid & 31) == 0) red[tid >> 5] = m;
    __syncthreads();
    {
        float t = (tid < 8) ? red[tid] : -1e30f;
#pragma unroll
        for (int o = 4; o > 0; o >>= 1) t = fmaxf(t, __shfl_xor_sync(0xffffffffu, t, o));
        if (tid == 0) red[0] = t;
    }
    __syncthreads();
    m = red[0];
    __syncthreads();

    float s = 0.f;
#pragma unroll
    for (int i = 0; i < 16; ++i) { v[i] = __expf(v[i] - m); s += v[i]; }
#pragma unroll
    for (int o = 16; o > 0; o >>= 1) s += __shfl_xor_sync(0xffffffffu, s, o);
    if ((tid & 31) == 0) red[tid >> 5] = s;
    __syncthreads();
    {
        float t = (tid < 8) ? red[tid] : 0.f;
#pragma unroll
        for (int o = 4; o > 0; o >>= 1) t += __shfl_xor_sync(0xffffffffu, t, o);
        if (tid == 0) red[0] = t;
    }
    __syncthreads();
    const float inv = 1.f / red[0];

#pragma unroll
    for (int i = 0; i < 4; ++i) {
        const long long base = row * (long long)SEQ + i * 1024 + tid * 4;
        __nv_bfloat16 h[4], l[4];
#pragma unroll
        for (int q = 0; q < 4; ++q) {
            const float f = v[4 * i + q] * inv;
            h[q] = __float2bfloat16(f);
            l[q] = __float2bfloat16(f - __bfloat162float(h[q]));
        }
        __nv_bfloat162 h01, h23, l01, l23;
        h01.x = h[0]; h01.y = h[1]; h23.x = h[2]; h23.y = h[3];
        l01.x = l[0]; l01.y = l[1]; l23.x = l[2]; l23.y = l[3];
        *reinterpret_cast<__nv_bfloat162*>(Ph + base)     = h01;
        *reinterpret_cast<__nv_bfloat162*>(Ph + base + 2) = h23;
        *reinterpret_cast<__nv_bfloat162*>(Pl + base)     = l01;
        *reinterpret_cast<__nv_bfloat162*>(Pl + base + 2) = l23;
    }
}

// ---------------------------------------------------------------------------
extern "C" void kernel_launch(void* const* d_in, const int* in_sizes, int n_in,
                              void* d_out, int out_size)
{
    const float* x  = (const float*)d_in[0];
    const float* Wq = (const float*)d_in[1];
    const float* Wk = (const float*)d_in[2];
    const float* Wv = (const float*)d_in[3];
    float* out = (float*)d_out;

    __nv_bfloat16 *xh, *xl, *Wqh, *Wql, *Wkh, *Wkl, *Wvh, *Wvl;
    __nv_bfloat16 *Qh, *Ql, *Kh, *Kl, *VTh, *VTl, *Ph, *Pl;
    float* P;
    cudaGetSymbolAddress((void**)&xh, g_xh);   cudaGetSymbolAddress((void**)&xl, g_xl);
    cudaGetSymbolAddress((void**)&Wqh, g_Wqh); cudaGetSymbolAddress((void**)&Wql, g_Wql);
    cudaGetSymbolAddress((void**)&Wkh, g_Wkh); cudaGetSymbolAddress((void**)&Wkl, g_Wkl);
    cudaGetSymbolAddress((void**)&Wvh, g_Wvh); cudaGetSymbolAddress((void**)&Wvl, g_Wvl);
    cudaGetSymbolAddress((void**)&Qh, g_Qh);   cudaGetSymbolAddress((void**)&Ql, g_Ql);
    cudaGetSymbolAddress((void**)&Kh, g_Kh);   cudaGetSymbolAddress((void**)&Kl, g_Kl);
    cudaGetSymbolAddress((void**)&VTh, g_VTh); cudaGetSymbolAddress((void**)&VTl, g_VTl);
    cudaGetSymbolAddress((void**)&Ph, g_Ph);   cudaGetSymbolAddress((void**)&Pl, g_Pl);
    cudaGetSymbolAddress((void**)&P, g_P);

    cudaFuncSetAttribute(tc_gemm<0>, cudaFuncAttributeMaxDynamicSharedMemorySize, SMEM_BYTES);
    cudaFuncSetAttribute(tc_gemm<1>, cudaFuncAttributeMaxDynamicSharedMemorySize, SMEM_BYTES);
    cudaFuncSetAttribute(tc_gemm<2>, cudaFuncAttributeMaxDynamicSharedMemorySize, SMEM_BYTES);

    // 1. split inputs
    split_kernel<<<(MTOT * DIM / 4 + 255) / 256, 256>>>(x, xh, xl, MTOT * DIM / 4);
    wtrans_split<<<dim3(16, 16), dim3(32, 8)>>>(Wq, Wqh, Wql);
    wtrans_split<<<dim3(16, 16), dim3(32, 8)>>>(Wk, Wkh, Wkl);
    wtrans_split<<<dim3(16, 16), dim3(32, 8)>>>(Wv, Wvh, Wvl);

    // 2. projections: [8192,512] @ W^T[512,512]^T
    dim3 gp(DIM / 128, MTOT / 128, 1);
    tc_gemm<1><<<gp, 256, SMEM_BYTES>>>(xh, xl, Wqh, Wql, nullptr, Qh, Ql,
                                        MTOT, DIM, DIM, 0, 0, 0, 1.f);
    tc_gemm<1><<<gp, 256, SMEM_BYTES>>>(xh, xl, Wkh, Wkl, nullptr, Kh, Kl,
                                        MTOT, DIM, DIM, 0, 0, 0, 1.f);
    tc_gemm<2><<<gp, 256, SMEM_BYTES>>>(xh, xl, Wvh, Wvl, nullptr, VTh, VTl,
                                        MTOT, DIM, DIM, 0, 0, 0, 1.f);

    // 3. scores: per batch [4096,512] @ [4096,512]^T, scaled
    const float scale = 0.044194173824159216f;   // 1/sqrt(512)
    dim3 gs(SEQ / 128, SEQ / 128, BATCH);
    tc_gemm<0><<<gs, 256, SMEM_BYTES>>>(Qh, Ql, Kh, Kl, P, nullptr, nullptr,
                                        SEQ, SEQ, DIM,
                                        (long long)SEQ * DIM, (long long)SEQ * DIM,
                                        (long long)SEQ * SEQ, scale);

    // 4. softmax + split
    softmax_split<<<BATCH * SEQ, 256>>>(P, Ph, Pl);

    // 5. context: per batch [4096,4096] @ V^T[512,4096]^T -> out
    dim3 gv(DIM / 128, SEQ / 128, BATCH);
    tc_gemm<0><<<gv, 256, SMEM_BYTES>>>(Ph, Pl, VTh, VTl, out, nullptr, nullptr,
                                        SEQ, DIM, SEQ,
                                        (long long)SEQ * SEQ, (long long)DIM * SEQ,
                                        (long long)SEQ * DIM, 1.f);

    (void)in_sizes; (void)n_in; (void)out_size;
}

// round 4
// speedup vs baseline: 2.9970x; 1.2848x over previous
#include <cuda_runtime.h>
#include <cuda_bf16.h>
#include <cuda_fp16.h>
#include <cstdint>

#define BATCH 2
#define SEQ   4096
#define DIM   512
#define MTOT  (BATCH*SEQ)   // 8192

// ---------------------------------------------------------------------------
// Scratch (device globals; no allocations allowed).  All 16-bit tensors are
// stored as raw uint16_t; the consumer knows the real type (bf16 vs fp16).
// ---------------------------------------------------------------------------
__device__ __align__(128) uint16_t g_xh [MTOT*DIM], g_xl [MTOT*DIM];   // bf16
__device__ __align__(128) uint16_t g_Wqh[DIM*DIM],  g_Wql[DIM*DIM];    // bf16
__device__ __align__(128) uint16_t g_Wkh[DIM*DIM],  g_Wkl[DIM*DIM];    // bf16
__device__ __align__(128) uint16_t g_Wvh[DIM*DIM],  g_Wvl[DIM*DIM];    // bf16
__device__ __align__(128) uint16_t g_Qh [MTOT*DIM], g_Ql [MTOT*DIM];   // fp16
__device__ __align__(128) uint16_t g_Kh [MTOT*DIM];                    // fp16 (hi only)
__device__ __align__(128) uint16_t g_VTh[MTOT*DIM];                    // fp16 [B][DIM][SEQ]
__device__ __align__(128) float    g_P  [(long long)BATCH*SEQ*SEQ];
__device__ __align__(128) uint16_t g_Ph [(long long)BATCH*SEQ*SEQ];    // fp16
__device__ __align__(128) uint16_t g_Pl [(long long)BATCH*SEQ*SEQ];    // fp16

// ---------------------------------------------------------------------------
// PTX helpers (sm_80-era ISA only: mma.sync / ldmatrix / cp.async)
// ---------------------------------------------------------------------------
__device__ __forceinline__ uint32_t smem_u32(const void* p) {
    uint32_t a;
    asm("{ .reg .u64 t; cvta.to.shared.u64 t, %1; cvt.u32.u64 %0, t; }"
        : "=r"(a) : "l"(p));
    return a;
}

__device__ __forceinline__ void cp_async16(uint32_t saddr, const void* gptr) {
    asm volatile("cp.async.cg.shared.global [%0], [%1], 16;"
                 :: "r"(saddr), "l"(gptr) : "memory");
}
#define CP_COMMIT()  asm volatile("cp.async.commit_group;" ::: "memory")
#define CP_WAIT(n)   asm volatile("cp.async.wait_group %0;" :: "n"(n) : "memory")

__device__ __forceinline__ void ldsm_x4(uint32_t* r, uint32_t addr) {
    asm volatile("ldmatrix.sync.aligned.m8n8.x4.shared.b16 {%0,%1,%2,%3}, [%4];"
                 : "=r"(r[0]), "=r"(r[1]), "=r"(r[2]), "=r"(r[3]) : "r"(addr));
}
__device__ __forceinline__ void ldsm_x2(uint32_t* r, uint32_t addr) {
    asm volatile("ldmatrix.sync.aligned.m8n8.x2.shared.b16 {%0,%1}, [%2];"
                 : "=r"(r[0]), "=r"(r[1]) : "r"(addr));
}

__device__ __forceinline__ void mma_bf16(float* c, const uint32_t* a, const uint32_t* b) {
    asm volatile(
        "mma.sync.aligned.m16n8k16.row.col.f32.bf16.bf16.f32 "
        "{%0,%1,%2,%3}, {%4,%5,%6,%7}, {%8,%9}, {%0,%1,%2,%3};"
        : "+f"(c[0]), "+f"(c[1]), "+f"(c[2]), "+f"(c[3])
        : "r"(a[0]), "r"(a[1]), "r"(a[2]), "r"(a[3]), "r"(b[0]), "r"(b[1]));
}
__device__ __forceinline__ void mma_f16(float* c, const uint32_t* a, const uint32_t* b) {
    asm volatile(
        "mma.sync.aligned.m16n8k16.row.col.f32.f16.f16.f32 "
        "{%0,%1,%2,%3}, {%4,%5,%6,%7}, {%8,%9}, {%0,%1,%2,%3};"
        : "+f"(c[0]), "+f"(c[1]), "+f"(c[2]), "+f"(c[3])
        : "r"(a[0]), "r"(a[1]), "r"(a[2]), "r"(a[3]), "r"(b[0]), "r"(b[1]));
}

// ---------------------------------------------------------------------------
// Split GEMM on mma.sync:  C[M,N] = alpha * (A[M,K] @ B[N,K]^T)
//  SPLIT3=true : bf16, 3 MMAs (ah*bh + ah*bl + al*bh)   — projections
//  SPLIT3=false: fp16, 2 MMAs (ah*bh + al*bh), no Bl    — scores / PV
// BM=BN=128, BK=32, 256 threads (2x4 warps), warp tile 64x32.
// Double-buffered cp.async, pitch-80B smem rows (conflict-free ldmatrix).
// EPI: 0 = fp32 C
//      1 = fp16 hi+lo split (Ch, Cl)
//      2 = fp16 hi only (Ch)
//      3 = fp16 hi only, transposed V^T layout [B][DIM][SEQ]
// ---------------------------------------------------------------------------
constexpr int PITCH  = 80;               // 64B data + 16B pad
constexpr int TILE_B = 128 * PITCH;      // 10240 B per tile

template <int EPI, bool SPLIT3>
__global__ __launch_bounds__(256)
void tc_gemm(const uint16_t* __restrict__ Ah, const uint16_t* __restrict__ Al,
             const uint16_t* __restrict__ Bh, const uint16_t* __restrict__ Bl,
             float* __restrict__ C,
             uint16_t* __restrict__ Ch, uint16_t* __restrict__ Cl,
             int M, int N, int K,
             long long sA, long long sB, long long sC, float alpha)
{
    constexpr int NT      = SPLIT3 ? 4 : 3;
    constexpr int STAGE_B = NT * TILE_B;

    extern __shared__ __align__(128) char smem[];
    const uint32_t sb = smem_u32(smem);
    const int tid  = threadIdx.x;
    const int wid  = tid >> 5;
    const int lane = tid & 31;
    const int z = blockIdx.z;
    Ah += z * sA;  Al += z * sA;  Bh += z * sB;
    if (SPLIT3) Bl += z * sB;

    const long long bm = (long long)blockIdx.y * 128;
    const long long bn = (long long)blockIdx.x * 128;

    const uint16_t* srcs[4] = {
        Ah + bm * K, Al + bm * K, Bh + bn * K,
        SPLIT3 ? (Bl + bn * K) : (const uint16_t*)nullptr };

    // ---- async tile loader: NT tiles x 512 16B-chunks, 2 per thread/tile ----
    auto issue_load = [&](int it, int buf) {
        const uint32_t stage = sb + buf * STAGE_B;
        const int k0 = it * 32;
#pragma unroll
        for (int t = 0; t < NT; ++t) {
            const uint16_t* src = srcs[t] + k0;
#pragma unroll
            for (int c = 0; c < 2; ++c) {
                const int chunk = tid + c * 256;        // 0..511
                const int row = chunk >> 2;
                const int c4  = chunk & 3;
                cp_async16(stage + t * TILE_B + row * PITCH + c4 * 16,
                           src + (long long)row * K + c4 * 8);
            }
        }
    };

    const int warpM = wid >> 2;        // 0..1  (64 rows each)
    const int warpN = wid & 3;         // 0..3  (32 cols each)

    const int aRow = warpM * 64 + (lane & 15);
    const int aOff = (lane >> 4) * 16;
    const int bRow = warpN * 32 + (lane & 7);
    const int bOff = ((lane >> 3) & 1) * 16;

    float acc[4][4][4];
#pragma unroll
    for (int mi = 0; mi < 4; ++mi)
#pragma unroll
        for (int ni = 0; ni < 4; ++ni)
#pragma unroll
            for (int q = 0; q < 4; ++q) acc[mi][ni][q] = 0.f;

    const int niter = K / 32;
    issue_load(0, 0); CP_COMMIT();
    if (niter > 1) issue_load(1, 1);
    CP_COMMIT();

    for (int it = 0; it < niter; ++it) {
        const int buf = it & 1;
        CP_WAIT(1);
        __syncthreads();

        const uint32_t stage  = sb + buf * STAGE_B;
        const uint32_t aBaseH = stage + 0 * TILE_B + aRow * PITCH + aOff;
        const uint32_t aBaseL = stage + 1 * TILE_B + aRow * PITCH + aOff;
        const uint32_t bBaseH = stage + 2 * TILE_B + bRow * PITCH + bOff;
        const uint32_t bBaseL = stage + 3 * TILE_B + bRow * PITCH + bOff;

#pragma unroll
        for (int ks = 0; ks < 2; ++ks) {
            uint32_t ah[4][4], al[4][4], bh[4][2], bl[4][2];
#pragma unroll
            for (int mi = 0; mi < 4; ++mi) {
                ldsm_x4(ah[mi], aBaseH + mi * (16 * PITCH) + ks * 32);
                ldsm_x4(al[mi], aBaseL + mi * (16 * PITCH) + ks * 32);
            }
#pragma unroll
            for (int ni = 0; ni < 4; ++ni) {
                ldsm_x2(bh[ni], bBaseH + ni * (8 * PITCH) + ks * 32);
                if (SPLIT3) ldsm_x2(bl[ni], bBaseL + ni * (8 * PITCH) + ks * 32);
            }
#pragma unroll
            for (int mi = 0; mi < 4; ++mi)
#pragma unroll
                for (int ni = 0; ni < 4; ++ni) {
                    if (SPLIT3) {
                        mma_bf16(acc[mi][ni], ah[mi], bh[ni]);
                        mma_bf16(acc[mi][ni], ah[mi], bl[ni]);
                        mma_bf16(acc[mi][ni], al[mi], bh[ni]);
                    } else {
                        mma_f16(acc[mi][ni], ah[mi], bh[ni]);
                        mma_f16(acc[mi][ni], al[mi], bh[ni]);
                    }
                }
        }
        __syncthreads();
        if (it + 2 < niter) issue_load(it + 2, buf);
        CP_COMMIT();
    }

    // ---- epilogue ----
    const int r0 = warpM * 64 + (lane >> 2);
    const int c0 = warpN * 32 + (lane & 3) * 2;
#pragma unroll
    for (int mi = 0; mi < 4; ++mi) {
#pragma unroll
        for (int ni = 0; ni < 4; ++ni) {
#pragma unroll
            for (int h = 0; h < 2; ++h) {
                const long long row = bm + r0 + mi * 16 + h * 8;
                const int col = (int)bn + c0 + ni * 8;
                const float f0 = acc[mi][ni][2 * h]     * alpha;
                const float f1 = acc[mi][ni][2 * h + 1] * alpha;
                if (EPI == 0) {
                    float2 v; v.x = f0; v.y = f1;
                    *reinterpret_cast<float2*>(C + z * sC + row * N + col) = v;
                } else if (EPI == 1) {
                    __half h0 = __float2half_rn(f0);
                    __half l0 = __float2half_rn(f0 - __half2float(h0));
                    __half h1 = __float2half_rn(f1);
                    __half l1 = __float2half_rn(f1 - __half2float(h1));
                    __half2 vh; vh.x = h0; vh.y = h1;
                    __half2 vl; vl.x = l0; vl.y = l1;
                    *reinterpret_cast<__half2*>(Ch + row * N + col) = vh;
                    *reinterpret_cast<__half2*>(Cl + row * N + col) = vl;
                } else if (EPI == 2) {
                    __half2 vh; vh.x = __float2half_rn(f0); vh.y = __float2half_rn(f1);
                    *reinterpret_cast<__half2*>(Ch + row * N + col) = vh;
                } else {
                    // V^T layout [B][DIM][SEQ]; row = token, col = d
                    const long long bimg = (row >> 12) * ((long long)DIM * SEQ);
                    const int s = (int)(row & (SEQ - 1));
                    reinterpret_cast<__half*>(Ch)[bimg + (long long)col * SEQ + s] =
                        __float2half_rn(f0);
                    reinterpret_cast<__half*>(Ch)[bimg + (long long)(col + 1) * SEQ + s] =
                        __float2half_rn(f1);
                }
            }
        }
    }
}

// ---------------------------------------------------------------------------
// fp32 -> bf16 hi/lo split (elementwise, float4 vectorized)
// ---------------------------------------------------------------------------
__global__ __launch_bounds__(256)
void split_kernel(const float* __restrict__ in,
                  uint16_t* __restrict__ hi, uint16_t* __restrict__ lo, int n4)
{
    const int i = blockIdx.x * blockDim.x + threadIdx.x;
    if (i >= n4) return;
    float4 v = *reinterpret_cast<const float4*>(in + 4 * (long long)i);
    float f[4] = { v.x, v.y, v.z, v.w };
    __nv_bfloat16 h[4], l[4];
#pragma unroll
    for (int q = 0; q < 4; ++q) {
        h[q] = __float2bfloat16(f[q]);
        l[q] = __float2bfloat16(f[q] - __bfloat162float(h[q]));
    }
    __nv_bfloat162 h01, h23, l01, l23;
    h01.x = h[0]; h01.y = h[1]; h23.x = h[2]; h23.y = h[3];
    l01.x = l[0]; l01.y = l[1]; l23.x = l[2]; l23.y = l[3];
    *reinterpret_cast<__nv_bfloat162*>(hi + 4 * (long long)i)     = h01;
    *reinterpret_cast<__nv_bfloat162*>(hi + 4 * (long long)i + 2) = h23;
    *reinterpret_cast<__nv_bfloat162*>(lo + 4 * (long long)i)     = l01;
    *reinterpret_cast<__nv_bfloat162*>(lo + 4 * (long long)i + 2) = l23;
}

// ---------------------------------------------------------------------------
// W[i][o] -> W^T[o][i], split to bf16 hi/lo.  512x512.
// ---------------------------------------------------------------------------
__global__ __launch_bounds__(256)
void wtrans_split(const float* __restrict__ W,
                  uint16_t* __restrict__ Th, uint16_t* __restrict__ Tl)
{
    __shared__ float t[32][33];
    const int bx = blockIdx.x * 32;   // o
    const int by = blockIdx.y * 32;   // i
    const int tx = threadIdx.x, ty = threadIdx.y;   // 32 x 8
#pragma unroll
    for (int r = ty; r < 32; r += 8)
        t[r][tx] = W[(by + r) * DIM + bx + tx];
    __syncthreads();
#pragma unroll
    for (int r = ty; r < 32; r += 8) {
        const float f = t[tx][r];                    // = W[by+tx][bx+r]
        __nv_bfloat16 h = __float2bfloat16(f);
        __nv_bfloat16 l = __float2bfloat16(f - __bfloat162float(h));
        reinterpret_cast<__nv_bfloat16*>(Th)[(bx + r) * DIM + by + tx] = h;
        reinterpret_cast<__nv_bfloat16*>(Tl)[(bx + r) * DIM + by + tx] = l;
    }
}

// ---------------------------------------------------------------------------
// Row softmax over 4096-wide rows; writes fp16 hi/lo split directly.
// ---------------------------------------------------------------------------
__global__ __launch_bounds__(256)
void softmax_split(const float* __restrict__ P,
                   uint16_t* __restrict__ Ph, uint16_t* __restrict__ Pl)
{
    const long long row = blockIdx.x;
    const float* p = P + row * (long long)SEQ;
    const int tid = threadIdx.x;

    __shared__ float red[8];

    float v[16];
#pragma unroll
    for (int i = 0; i < 4; ++i)
        *reinterpret_cast<float4*>(v + 4 * i) =
            *reinterpret_cast<const float4*>(p + i * 1024 + tid * 4);

    float m = -1e30f;
#pragma unroll
    for (int i = 0; i < 16; ++i) m = fmaxf(m, v[i]);
#pragma unroll
    for (int o = 16; o > 0; o >>= 1) m = fmaxf(m, __shfl_xor_sync(0xffffffffu, m, o));
    if ((tid & 31) == 0) red[tid >> 5] = m;
    __syncthreads();
    {
        float t = (tid < 8) ? red[tid] : -1e30f;
#pragma unroll
        for (int o = 4; o > 0; o >>= 1) t = fmaxf(t, __shfl_xor_sync(0xffffffffu, t, o));
        if (tid == 0) red[0] = t;
    }
    __syncthreads();
    m = red[0];
    __syncthreads();

    float s = 0.f;
#pragma unroll
    for (int i = 0; i < 16; ++i) { v[i] = __expf(v[i] - m); s += v[i]; }
#pragma unroll
    for (int o = 16; o > 0; o >>= 1) s += __shfl_xor_sync(0xffffffffu, s, o);
    if ((tid & 31) == 0) red[tid >> 5] = s;
    __syncthreads();
    {
        float t = (tid < 8) ? red[tid] : 0.f;
#pragma unroll
        for (int o = 4; o > 0; o >>= 1) t += __shfl_xor_sync(0xffffffffu, t, o);
        if (tid == 0) red[0] = t;
    }
    __syncthreads();
    const float inv = 1.f / red[0];

#pragma unroll
    for (int i = 0; i < 4; ++i) {
        const long long base = row * (long long)SEQ + i * 1024 + tid * 4;
        __half h[4], l[4];
#pragma unroll
        for (int q = 0; q < 4; ++q) {
            const float f = v[4 * i + q] * inv;
            h[q] = __float2half_rn(f);
            l[q] = __float2half_rn(f - __half2float(h[q]));
        }
        __half2 h01, h23, l01, l23;
        h01.x = h[0]; h01.y = h[1]; h23.x = h[2]; h23.y = h[3];
        l01.x = l[0]; l01.y = l[1]; l23.x = l[2]; l23.y = l[3];
        *reinterpret_cast<__half2*>(Ph + base)     = h01;
        *reinterpret_cast<__half2*>(Ph + base + 2) = h23;
        *reinterpret_cast<__half2*>(Pl + base)     = l01;
        *reinterpret_cast<__half2*>(Pl + base + 2) = l23;
    }
}

// ---------------------------------------------------------------------------
extern "C" void kernel_launch(void* const* d_in, const int* in_sizes, int n_in,
                              void* d_out, int out_size)
{
    const float* x  = (const float*)d_in[0];
    const float* Wq = (const float*)d_in[1];
    const float* Wk = (const float*)d_in[2];
    const float* Wv = (const float*)d_in[3];
    float* out = (float*)d_out;

    uint16_t *xh, *xl, *Wqh, *Wql, *Wkh, *Wkl, *Wvh, *Wvl;
    uint16_t *Qh, *Ql, *Kh, *VTh, *Ph, *Pl;
    float* P;
    cudaGetSymbolAddress((void**)&xh, g_xh);   cudaGetSymbolAddress((void**)&xl, g_xl);
    cudaGetSymbolAddress((void**)&Wqh, g_Wqh); cudaGetSymbolAddress((void**)&Wql, g_Wql);
    cudaGetSymbolAddress((void**)&Wkh, g_Wkh); cudaGetSymbolAddress((void**)&Wkl, g_Wkl);
    cudaGetSymbolAddress((void**)&Wvh, g_Wvh); cudaGetSymbolAddress((void**)&Wvl, g_Wvl);
    cudaGetSymbolAddress((void**)&Qh, g_Qh);   cudaGetSymbolAddress((void**)&Ql, g_Ql);
    cudaGetSymbolAddress((void**)&Kh, g_Kh);
    cudaGetSymbolAddress((void**)&VTh, g_VTh);
    cudaGetSymbolAddress((void**)&Ph, g_Ph);   cudaGetSymbolAddress((void**)&Pl, g_Pl);
    cudaGetSymbolAddress((void**)&P, g_P);

    constexpr int SM3 = 2 * 4 * TILE_B;   // 81920  (bf16 3-MMA path)
    constexpr int SM2 = 2 * 3 * TILE_B;   // 61440  (fp16 2-MMA path)
    cudaFuncSetAttribute(tc_gemm<1, true>,  cudaFuncAttributeMaxDynamicSharedMemorySize, SM3);
    cudaFuncSetAttribute(tc_gemm<2, true>,  cudaFuncAttributeMaxDynamicSharedMemorySize, SM3);
    cudaFuncSetAttribute(tc_gemm<3, true>,  cudaFuncAttributeMaxDynamicSharedMemorySize, SM3);
    cudaFuncSetAttribute(tc_gemm<0, false>, cudaFuncAttributeMaxDynamicSharedMemorySize, SM2);

    // 1. split inputs (bf16 hi/lo for the 3-MMA projection GEMMs)
    split_kernel<<<(MTOT * DIM / 4 + 255) / 256, 256>>>(x, xh, xl, MTOT * DIM / 4);
    wtrans_split<<<dim3(16, 16), dim3(32, 8)>>>(Wq, Wqh, Wql);
    wtrans_split<<<dim3(16, 16), dim3(32, 8)>>>(Wk, Wkh, Wkl);
    wtrans_split<<<dim3(16, 16), dim3(32, 8)>>>(Wv, Wvh, Wvl);

    // 2. projections (bf16 3-MMA): Q -> fp16 hi+lo, K -> fp16 hi, V -> fp16 hi V^T
    dim3 gp(DIM / 128, MTOT / 128, 1);
    tc_gemm<1, true><<<gp, 256, SM3>>>(xh, xl, Wqh, Wql, nullptr, Qh, Ql,
                                       MTOT, DIM, DIM, 0, 0, 0, 1.f);
    tc_gemm<2, true><<<gp, 256, SM3>>>(xh, xl, Wkh, Wkl, nullptr, Kh, nullptr,
                                       MTOT, DIM, DIM, 0, 0, 0, 1.f);
    tc_gemm<3, true><<<gp, 256, SM3>>>(xh, xl, Wvh, Wvl, nullptr, VTh, nullptr,
                                       MTOT, DIM, DIM, 0, 0, 0, 1.f);

    // 3. scores (fp16 2-MMA): per batch [4096,512] @ [4096,512]^T, scaled
    const float scale = 0.044194173824159216f;   // 1/sqrt(512)
    dim3 gs(SEQ / 128, SEQ / 128, BATCH);
    tc_gemm<0, false><<<gs, 256, SM2>>>(Qh, Ql, Kh, nullptr, P, nullptr, nullptr,
                                        SEQ, SEQ, DIM,
                                        (long long)SEQ * DIM, (long long)SEQ * DIM,
                                        (long long)SEQ * SEQ, scale);

    // 4. softmax + fp16 hi/lo split
    softmax_split<<<BATCH * SEQ, 256>>>(P, Ph, Pl);

    // 5. context (fp16 2-MMA): per batch [4096,4096] @ V^T[512,4096]^T -> out
    dim3 gv(DIM / 128, SEQ / 128, BATCH);
    tc_gemm<0, false><<<gv, 256, SM2>>>(Ph, Pl, VTh, nullptr, out, nullptr, nullptr,
                                        SEQ, DIM, SEQ,
                                        (long long)SEQ * SEQ, (long long)DIM * SEQ,
                                        (long long)SEQ * DIM, 1.f);

    (void)in_sizes; (void)n_in; (void)out_size;
}

// round 5
// speedup vs baseline: 5.2805x; 1.7619x over previous
#include <cuda_runtime.h>
#include <cuda_bf16.h>
#include <cuda_fp16.h>
#include <cstdint>

#define BATCH 2
#define SEQ   4096
#define DIM   512
#define MTOT  (BATCH*SEQ)   // 8192

// ---------------------------------------------------------------------------
// Scratch (device globals; no allocations allowed)
// ---------------------------------------------------------------------------
__device__ __align__(128) uint16_t g_xh [MTOT*DIM], g_xl [MTOT*DIM];   // bf16
__device__ __align__(128) uint16_t g_Wqh[DIM*DIM],  g_Wql[DIM*DIM];    // bf16
__device__ __align__(128) uint16_t g_Wkh[DIM*DIM],  g_Wkl[DIM*DIM];    // bf16
__device__ __align__(128) uint16_t g_Wvh[DIM*DIM],  g_Wvl[DIM*DIM];    // bf16
__device__ __align__(128) uint16_t g_Qh [MTOT*DIM];                    // fp16
__device__ __align__(128) uint16_t g_Kh [MTOT*DIM];                    // fp16
__device__ __align__(128) uint16_t g_VTh[MTOT*DIM];                    // fp16 [B][DIM][SEQ]
__device__ __align__(128) uint16_t g_Ph [(long long)BATCH*SEQ*SEQ];    // fp16 exp(scores)
__device__ __align__(128) float    g_RInv[MTOT];                       // 1/rowsum

// ---------------------------------------------------------------------------
// PTX helpers (sm_80-era ISA only)
// ---------------------------------------------------------------------------
__device__ __forceinline__ uint32_t smem_u32(const void* p) {
    uint32_t a;
    asm("{ .reg .u64 t; cvta.to.shared.u64 t, %1; cvt.u32.u64 %0, t; }"
        : "=r"(a) : "l"(p));
    return a;
}
__device__ __forceinline__ void cp_async16(uint32_t saddr, const void* gptr) {
    asm volatile("cp.async.cg.shared.global [%0], [%1], 16;"
                 :: "r"(saddr), "l"(gptr) : "memory");
}
#define CP_COMMIT()  asm volatile("cp.async.commit_group;" ::: "memory")
#define CP_WAIT(n)   asm volatile("cp.async.wait_group %0;" :: "n"(n) : "memory")

__device__ __forceinline__ void ldsm_x4(uint32_t* r, uint32_t addr) {
    asm volatile("ldmatrix.sync.aligned.m8n8.x4.shared.b16 {%0,%1,%2,%3}, [%4];"
                 : "=r"(r[0]), "=r"(r[1]), "=r"(r[2]), "=r"(r[3]) : "r"(addr));
}
__device__ __forceinline__ void ldsm_x2(uint32_t* r, uint32_t addr) {
    asm volatile("ldmatrix.sync.aligned.m8n8.x2.shared.b16 {%0,%1}, [%2];"
                 : "=r"(r[0]), "=r"(r[1]) : "r"(addr));
}
__device__ __forceinline__ void mma_bf16(float* c, const uint32_t* a, const uint32_t* b) {
    asm volatile(
        "mma.sync.aligned.m16n8k16.row.col.f32.bf16.bf16.f32 "
        "{%0,%1,%2,%3}, {%4,%5,%6,%7}, {%8,%9}, {%0,%1,%2,%3};"
        : "+f"(c[0]), "+f"(c[1]), "+f"(c[2]), "+f"(c[3])
        : "r"(a[0]), "r"(a[1]), "r"(a[2]), "r"(a[3]), "r"(b[0]), "r"(b[1]));
}
__device__ __forceinline__ void mma_f16(float* c, const uint32_t* a, const uint32_t* b) {
    asm volatile(
        "mma.sync.aligned.m16n8k16.row.col.f32.f16.f16.f32 "
        "{%0,%1,%2,%3}, {%4,%5,%6,%7}, {%8,%9}, {%0,%1,%2,%3};"
        : "+f"(c[0]), "+f"(c[1]), "+f"(c[2]), "+f"(c[3])
        : "r"(a[0]), "r"(a[1]), "r"(a[2]), "r"(a[3]), "r"(b[0]), "r"(b[1]));
}

// FMA-pipe exp (deg-6 2^f poly, rel err ~2e-7).  |x| < 30.
__device__ __forceinline__ float exp_fma(float x) {
    const float r = x * 1.4426950408889634f;
    const float i = rintf(r);
    const float f = r - i;
    float p = 1.5405906e-4f;
    p = fmaf(p, f, 1.3333558e-3f);
    p = fmaf(p, f, 9.6181291e-3f);
    p = fmaf(p, f, 5.5504109e-2f);
    p = fmaf(p, f, 2.4022651e-1f);
    p = fmaf(p, f, 6.9314718e-1f);
    p = fmaf(p, f, 1.0f);
    return p * __int_as_float(((int)i + 127) << 23);
}

// ---------------------------------------------------------------------------
// Split GEMM on mma.sync:  C[M,N] = alpha * (A[M,K] @ B[N,K]^T)
//  NMMA=3 : bf16, 3 MMAs (ah*bh + ah*bl + al*bh)  — projections
//  NMMA=1 : fp16, 1 MMA  (ah*bh)                  — scores / PV
// BM=BN=128, BK=32, 256 threads (2x4 warps), warp tile 64x32.
// Double-buffered cp.async, pitch-80B smem rows (conflict-free ldmatrix).
// EPI: 2 = fp16 hi (Ch);  3 = fp16 hi, V^T layout [B][DIM][SEQ];
//      4 = fp16 exp(f)    (scores -> unnormalized softmax numerators);
//      5 = fp32 * rowscale[row]  (PV with folded softmax normalization)
// ---------------------------------------------------------------------------
constexpr int PITCH  = 80;               // 64B data + 16B pad
constexpr int TILE_B = 128 * PITCH;      // 10240 B per tile

template <int EPI, int NMMA, int MINB>
__global__ __launch_bounds__(256, MINB)
void tc_gemm(const uint16_t* __restrict__ Ah, const uint16_t* __restrict__ Al,
             const uint16_t* __restrict__ Bh, const uint16_t* __restrict__ Bl,
             uint16_t* __restrict__ Ch, float* __restrict__ C,
             const float* __restrict__ rowscale,
             int M, int N, int K,
             long long sA, long long sB, long long sC, float alpha)
{
    constexpr int NT      = (NMMA == 3) ? 4 : 2;
    constexpr int STAGE_B = NT * TILE_B;

    extern __shared__ __align__(128) char smem[];
    const uint32_t sb = smem_u32(smem);
    const int tid  = threadIdx.x;
    const int wid  = tid >> 5;
    const int lane = tid & 31;
    const int z = blockIdx.z;
    Ah += z * sA;  Bh += z * sB;
    if (NMMA == 3) { Al += z * sA;  Bl += z * sB; }
    if (EPI == 4) Ch += z * sC;
    if (EPI == 5) { C += z * sC;  rowscale += z * M; }

    const long long bm = (long long)blockIdx.y * 128;
    const long long bn = (long long)blockIdx.x * 128;

    const uint16_t* srcs[NT];
    if (NMMA == 3) {
        srcs[0] = Ah + bm * K;  srcs[1] = Al + bm * K;
        srcs[2] = Bh + bn * K;  srcs[3] = Bl + bn * K;
    } else {
        srcs[0] = Ah + bm * K;  srcs[1] = Bh + bn * K;
    }

    auto issue_load = [&](int it, int buf) {
        const uint32_t stage = sb + buf * STAGE_B;
        const int k0 = it * 32;
#pragma unroll
        for (int t = 0; t < NT; ++t) {
            const uint16_t* src = srcs[t] + k0;
#pragma unroll
            for (int c = 0; c < 2; ++c) {
                const int chunk = tid + c * 256;        // 0..511
                const int row = chunk >> 2;
                const int c4  = chunk & 3;
                cp_async16(stage + t * TILE_B + row * PITCH + c4 * 16,
                           src + (long long)row * K + c4 * 8);
            }
        }
    };

    const int warpM = wid >> 2;        // 0..1  (64 rows each)
    const int warpN = wid & 3;         // 0..3  (32 cols each)
    const int aRow = warpM * 64 + (lane & 15);
    const int aOff = (lane >> 4) * 16;
    const int bRow = warpN * 32 + (lane & 7);
    const int bOff = ((lane >> 3) & 1) * 16;

    float acc[4][4][4];
#pragma unroll
    for (int mi = 0; mi < 4; ++mi)
#pragma unroll
        for (int ni = 0; ni < 4; ++ni)
#pragma unroll
            for (int q = 0; q < 4; ++q) acc[mi][ni][q] = 0.f;

    const int niter = K / 32;
    issue_load(0, 0); CP_COMMIT();
    if (niter > 1) issue_load(1, 1);
    CP_COMMIT();

    for (int it = 0; it < niter; ++it) {
        const int buf = it & 1;
        CP_WAIT(1);
        __syncthreads();

        const uint32_t stage  = sb + buf * STAGE_B;
        const uint32_t aBaseH = stage + aRow * PITCH + aOff;
        const uint32_t aBaseL = stage + 1 * TILE_B + aRow * PITCH + aOff;
        const uint32_t bBaseH = stage + (NT == 4 ? 2 : 1) * TILE_B + bRow * PITCH + bOff;
        const uint32_t bBaseL = stage + 3 * TILE_B + bRow * PITCH + bOff;

#pragma unroll
        for (int ks = 0; ks < 2; ++ks) {
            uint32_t ah[4][4], al[4][4], bh[4][2], bl[4][2];
#pragma unroll
            for (int mi = 0; mi < 4; ++mi) {
                ldsm_x4(ah[mi], aBaseH + mi * (16 * PITCH) + ks * 32);
                if (NMMA == 3) ldsm_x4(al[mi], aBaseL + mi * (16 * PITCH) + ks * 32);
            }
#pragma unroll
            for (int ni = 0; ni < 4; ++ni) {
                ldsm_x2(bh[ni], bBaseH + ni * (8 * PITCH) + ks * 32);
                if (NMMA == 3) ldsm_x2(bl[ni], bBaseL + ni * (8 * PITCH) + ks * 32);
            }
#pragma unroll
            for (int mi = 0; mi < 4; ++mi)
#pragma unroll
                for (int ni = 0; ni < 4; ++ni) {
                    if (NMMA == 3) {
                        mma_bf16(acc[mi][ni], ah[mi], bh[ni]);
                        mma_bf16(acc[mi][ni], ah[mi], bl[ni]);
                        mma_bf16(acc[mi][ni], al[mi], bh[ni]);
                    } else {
                        mma_f16(acc[mi][ni], ah[mi], bh[ni]);
                    }
                }
        }
        __syncthreads();
        if (it + 2 < niter) issue_load(it + 2, buf);
        CP_COMMIT();
    }

    // ---- epilogue ----
    const int r0 = warpM * 64 + (lane >> 2);
    const int c0 = warpN * 32 + (lane & 3) * 2;
#pragma unroll
    for (int mi = 0; mi < 4; ++mi) {
#pragma unroll
        for (int ni = 0; ni < 4; ++ni) {
#pragma unroll
            for (int h = 0; h < 2; ++h) {
                const long long row = bm + r0 + mi * 16 + h * 8;
                const int col = (int)bn + c0 + ni * 8;
                const float f0 = acc[mi][ni][2 * h]     * alpha;
                const float f1 = acc[mi][ni][2 * h + 1] * alpha;
                if (EPI == 2) {
                    __half2 v; v.x = __float2half_rn(f0); v.y = __float2half_rn(f1);
                    *reinterpret_cast<__half2*>(Ch + row * N + col) = v;
                } else if (EPI == 3) {
                    // V^T layout [B][DIM][SEQ]; row = token, col = d
                    const long long bimg = (row >> 12) * ((long long)DIM * SEQ);
                    const int s = (int)(row & (SEQ - 1));
                    reinterpret_cast<__half*>(Ch)[bimg + (long long)col * SEQ + s] =
                        __float2half_rn(f0);
                    reinterpret_cast<__half*>(Ch)[bimg + (long long)(col + 1) * SEQ + s] =
                        __float2half_rn(f1);
                } else if (EPI == 4) {
                    // unnormalized softmax numerators; split exp across MUFU+FMA pipes
                    const float e0 = __expf(f0);
                    const float e1 = exp_fma(f1);
                    __half2 v; v.x = __float2half_rn(e0); v.y = __float2half_rn(e1);
                    *reinterpret_cast<__half2*>(Ch + row * N + col) = v;
                } else {
                    const float rs = rowscale[row];
                    float2 v; v.x = f0 * rs; v.y = f1 * rs;
                    *reinterpret_cast<float2*>(C + row * N + col) = v;
                }
            }
        }
    }
}

// ---------------------------------------------------------------------------
// fp32 -> bf16 hi/lo split (elementwise, float4 vectorized)
// ---------------------------------------------------------------------------
__global__ __launch_bounds__(256)
void split_kernel(const float* __restrict__ in,
                  uint16_t* __restrict__ hi, uint16_t* __restrict__ lo, int n4)
{
    const int i = blockIdx.x * blockDim.x + threadIdx.x;
    if (i >= n4) return;
    float4 v = *reinterpret_cast<const float4*>(in + 4 * (long long)i);
    float f[4] = { v.x, v.y, v.z, v.w };
    __nv_bfloat16 h[4], l[4];
#pragma unroll
    for (int q = 0; q < 4; ++q) {
        h[q] = __float2bfloat16(f[q]);
        l[q] = __float2bfloat16(f[q] - __bfloat162float(h[q]));
    }
    __nv_bfloat162 h01, h23, l01, l23;
    h01.x = h[0]; h01.y = h[1]; h23.x = h[2]; h23.y = h[3];
    l01.x = l[0]; l01.y = l[1]; l23.x = l[2]; l23.y = l[3];
    *reinterpret_cast<__nv_bfloat162*>(hi + 4 * (long long)i)     = h01;
    *reinterpret_cast<__nv_bfloat162*>(hi + 4 * (long long)i + 2) = h23;
    *reinterpret_cast<__nv_bfloat162*>(lo + 4 * (long long)i)     = l01;
    *reinterpret_cast<__nv_bfloat162*>(lo + 4 * (long long)i + 2) = l23;
}

// ---------------------------------------------------------------------------
// W[i][o] -> W^T[o][i], split to bf16 hi/lo.  512x512.
// ---------------------------------------------------------------------------
__global__ __launch_bounds__(256)
void wtrans_split(const float* __restrict__ W,
                  uint16_t* __restrict__ Th, uint16_t* __restrict__ Tl)
{
    __shared__ float t[32][33];
    const int bx = blockIdx.x * 32;   // o
    const int by = blockIdx.y * 32;   // i
    const int tx = threadIdx.x, ty = threadIdx.y;   // 32 x 8
#pragma unroll
    for (int r = ty; r < 32; r += 8)
        t[r][tx] = W[(by + r) * DIM + bx + tx];
    __syncthreads();
#pragma unroll
    for (int r = ty; r < 32; r += 8) {
        const float f = t[tx][r];                    // = W[by+tx][bx+r]
        __nv_bfloat16 h = __float2bfloat16(f);
        __nv_bfloat16 l = __float2bfloat16(f - __bfloat162float(h));
        reinterpret_cast<__nv_bfloat16*>(Th)[(bx + r) * DIM + by + tx] = h;
        reinterpret_cast<__nv_bfloat16*>(Tl)[(bx + r) * DIM + by + tx] = l;
    }
}

// ---------------------------------------------------------------------------
// Row sums of Ph (fp16, 8192 rows x 4096) -> 1/sum (fp32)
// ---------------------------------------------------------------------------
__global__ __launch_bounds__(256)
void rowsum_inv(const uint16_t* __restrict__ Ph, float* __restrict__ inv)
{
    const long long row = blockIdx.x;
    const __half2* p = reinterpret_cast<const __half2*>(Ph + row * (long long)SEQ);
    const int tid = threadIdx.x;
    __shared__ float red[8];

    float s = 0.f;
#pragma unroll
    for (int i = 0; i < 8; ++i) {
        const __half2 h2 = p[tid + i * 256];
        const float2 f2 = __half22float2(h2);
        s += f2.x + f2.y;
    }
#pragma unroll
    for (int o = 16; o > 0; o >>= 1) s += __shfl_xor_sync(0xffffffffu, s, o);
    if ((tid & 31) == 0) red[tid >> 5] = s;
    __syncthreads();
    if (tid < 32) {
        float t = (tid < 8) ? red[tid] : 0.f;
#pragma unroll
        for (int o = 4; o > 0; o >>= 1) t += __shfl_xor_sync(0xffffffffu, t, o);
        if (tid == 0) inv[row] = 1.f / t;
    }
}

// ---------------------------------------------------------------------------
extern "C" void kernel_launch(void* const* d_in, const int* in_sizes, int n_in,
                              void* d_out, int out_size)
{
    const float* x  = (const float*)d_in[0];
    const float* Wq = (const float*)d_in[1];
    const float* Wk = (const float*)d_in[2];
    const float* Wv = (const float*)d_in[3];
    float* out = (float*)d_out;

    uint16_t *xh, *xl, *Wqh, *Wql, *Wkh, *Wkl, *Wvh, *Wvl;
    uint16_t *Qh, *Kh, *VTh, *Ph;
    float* rinv;
    cudaGetSymbolAddress((void**)&xh, g_xh);   cudaGetSymbolAddress((void**)&xl, g_xl);
    cudaGetSymbolAddress((void**)&Wqh, g_Wqh); cudaGetSymbolAddress((void**)&Wql, g_Wql);
    cudaGetSymbolAddress((void**)&Wkh, g_Wkh); cudaGetSymbolAddress((void**)&Wkl, g_Wkl);
    cudaGetSymbolAddress((void**)&Wvh, g_Wvh); cudaGetSymbolAddress((void**)&Wvl, g_Wvl);
    cudaGetSymbolAddress((void**)&Qh, g_Qh);
    cudaGetSymbolAddress((void**)&Kh, g_Kh);
    cudaGetSymbolAddress((void**)&VTh, g_VTh);
    cudaGetSymbolAddress((void**)&Ph, g_Ph);
    cudaGetSymbolAddress((void**)&rinv, g_RInv);

    constexpr int SM3 = 2 * 4 * TILE_B;   // 81920  (bf16 3-MMA path)
    constexpr int SM1 = 2 * 2 * TILE_B;   // 40960  (fp16 1-MMA path)
    cudaFuncSetAttribute(tc_gemm<2, 3, 1>, cudaFuncAttributeMaxDynamicSharedMemorySize, SM3);
    cudaFuncSetAttribute(tc_gemm<3, 3, 1>, cudaFuncAttributeMaxDynamicSharedMemorySize, SM3);
    cudaFuncSetAttribute(tc_gemm<4, 1, 2>, cudaFuncAttributeMaxDynamicSharedMemorySize, SM1);
    cudaFuncSetAttribute(tc_gemm<5, 1, 2>, cudaFuncAttributeMaxDynamicSharedMemorySize, SM1);

    // 1. split inputs (bf16 hi/lo for the 3-MMA projection GEMMs)
    split_kernel<<<(MTOT * DIM / 4 + 255) / 256, 256>>>(x, xh, xl, MTOT * DIM / 4);
    wtrans_split<<<dim3(16, 16), dim3(32, 8)>>>(Wq, Wqh, Wql);
    wtrans_split<<<dim3(16, 16), dim3(32, 8)>>>(Wk, Wkh, Wkl);
    wtrans_split<<<dim3(16, 16), dim3(32, 8)>>>(Wv, Wvh, Wvl);

    // 2. projections (bf16 3-MMA): Q,K -> fp16 hi;  V -> fp16 hi, V^T layout
    dim3 gp(DIM / 128, MTOT / 128, 1);
    tc_gemm<2, 3, 1><<<gp, 256, SM3>>>(xh, xl, Wqh, Wql, Qh, nullptr, nullptr,
                                       MTOT, DIM, DIM, 0, 0, 0, 1.f);
    tc_gemm<2, 3, 1><<<gp, 256, SM3>>>(xh, xl, Wkh, Wkl, Kh, nullptr, nullptr,
                                       MTOT, DIM, DIM, 0, 0, 0, 1.f);
    tc_gemm<3, 3, 1><<<gp, 256, SM3>>>(xh, xl, Wvh, Wvl, VTh, nullptr, nullptr,
                                       MTOT, DIM, DIM, 0, 0, 0, 1.f);

    // 3. scores (fp16 1-MMA) + fused exp: Ph = exp(Q K^T / sqrt(512)), fp16
    const float scale = 0.044194173824159216f;   // 1/sqrt(512)
    dim3 gs(SEQ / 128, SEQ / 128, BATCH);
    tc_gemm<4, 1, 2><<<gs, 256, SM1>>>(Qh, nullptr, Kh, nullptr, Ph, nullptr, nullptr,
                                       SEQ, SEQ, DIM,
                                       (long long)SEQ * DIM, (long long)SEQ * DIM,
                                       (long long)SEQ * SEQ, scale);

    // 4. row sums -> 1/sum
    rowsum_inv<<<MTOT, 256>>>(Ph, rinv);

    // 5. context (fp16 1-MMA) with folded normalization: out = (Ph VTh^T) / rowsum
    dim3 gv(DIM / 128, SEQ / 128, BATCH);
    tc_gemm<5, 1, 2><<<gv, 256, SM1>>>(Ph, nullptr, VTh, nullptr, nullptr, out, rinv,
                                       SEQ, DIM, SEQ,
                                       (long long)SEQ * SEQ, (long long)DIM * SEQ,
                                       (long long)SEQ * DIM, 1.f);

    (void)in_sizes; (void)n_in; (void)out_size;
}